// round 15
// baseline (speedup 1.0000x reference)
#include <cuda_runtime.h>
#include <cstdint>

#define NB 8192
#define NPARAM 4849
#define NPPAD 4864     // padded N (38*128)
#define PPAD 4864      // param row stride
#define NH 96
#define KSP 288        // term-major split K: A=[ah|ah|al], B=[bh|bl|bh]
#define NSTEPS 20

// Device-global scratch (allocation-free per harness rules)
__device__ float g_params[(size_t)NB * PPAD];     // 159 MB
__device__ float g_A[(size_t)NB * KSP];           // 9.4 MB
__device__ float g_B[(size_t)NPPAD * KSP];        // 5.6 MB

__device__ __forceinline__ float sigmoidf(float z) {
    return 1.0f / (1.0f + __expf(-z));
}
__device__ __forceinline__ float tf32_rn(float v) {
    uint32_t t;
    asm("cvt.rna.tf32.f32 %0, %1;" : "=r"(t) : "f"(v));
    return __uint_as_float(t);
}
__device__ __forceinline__ uint32_t smem_u32(const void* p) {
    uint32_t a;
    asm("{ .reg .u64 t; cvta.to.shared.u64 t, %1; cvt.u32.u64 %0, t; }" : "=r"(a) : "l"(p));
    return a;
}
__device__ __forceinline__ void cpa16(uint32_t dst, const void* src) {
    asm volatile("cp.async.ca.shared.global [%0], [%1], 16;" :: "r"(dst), "l"(src));
}

// ---------------------------------------------------------------------------
// Prep A: h = relu(...); tf32 hi/lo split, term-major row [ah | ah | al]
// ---------------------------------------------------------------------------
__global__ void prep_a_kernel(const float* __restrict__ x, const float* __restrict__ c,
                              const float* __restrict__ hw1, const float* __restrict__ hb1) {
    int idx = blockIdx.x * blockDim.x + threadIdx.x;
    if (idx >= NB * NH) return;
    int b = idx / NH;
    int k = idx - b * NH;
    float v = fmaf(hw1[2 * k], x[b], fmaf(hw1[2 * k + 1], c[b], hb1[k]));
    v = fmaxf(v, 0.0f);
    float hi = tf32_rn(v);
    float lo = tf32_rn(v - hi);
    size_t base = (size_t)b * KSP;
    g_A[base + k]       = hi;
    g_A[base + 96 + k]  = hi;
    g_A[base + 192 + k] = lo;
}

// ---------------------------------------------------------------------------
// Prep B: tf32 split of hw2 (rows >= NPARAM zeroed), term-major [bh | bl | bh]
// ---------------------------------------------------------------------------
__global__ void prep_b_kernel(const float* __restrict__ hw2) {
    int idx = blockIdx.x * blockDim.x + threadIdx.x;
    if (idx >= NPPAD * NH) return;
    int j = idx / NH;
    int k = idx - j * NH;
    float w = (j < NPARAM) ? hw2[j * NH + k] : 0.0f;
    float hi = tf32_rn(w);
    float lo = tf32_rn(w - hi);
    size_t base = (size_t)j * KSP;
    g_B[base + k]       = hi;
    g_B[base + 96 + k]  = lo;
    g_B[base + 192 + k] = hi;
}

// ---------------------------------------------------------------------------
// 3xTF32 GEMM, cp.async double-buffered.  128x128 tile, K=288 in 6 chunks of
// 48.  Stage = A[128][52] + B[128][52] fp32 = 53.2 KB; 2 stages = 106.5 KB
// -> 2 CTAs/SM.  8 warps: warp (wm 0..3, wn 0..1) computes 32x64.
// ---------------------------------------------------------------------------
#define CHK 48
#define SP 52                                   // pitch: rows 16B-aligned, frag LDS conflict-free
#define STAGEF (2 * 128 * SP)                   // floats per stage (A then B)
#define GT_SMEM (2 * STAGEF * 4)                // 106496 bytes

__device__ __forceinline__ void mma1688_tf32(float* c, const uint32_t* a, const uint32_t* b) {
    asm volatile(
        "mma.sync.aligned.m16n8k8.row.col.f32.tf32.tf32.f32 "
        "{%0,%1,%2,%3}, {%4,%5,%6,%7}, {%8,%9}, {%0,%1,%2,%3};"
        : "+f"(c[0]), "+f"(c[1]), "+f"(c[2]), "+f"(c[3])
        : "r"(a[0]), "r"(a[1]), "r"(a[2]), "r"(a[3]), "r"(b[0]), "r"(b[1]));
}

__global__ __launch_bounds__(256, 2) void gemm_mma_kernel(const float* __restrict__ hb2) {
    extern __shared__ __align__(16) float sm[];

    const int tid = threadIdx.x;
    const int wid = tid >> 5;
    const int lid = tid & 31;
    const int b0 = blockIdx.x * 128;
    const int j0 = blockIdx.y * 128;

    // cp.async load of chunk c into stage st: 6 float4 for A + 6 for B per thread
    auto load_chunk = [&](int c, int st) {
        float* As = sm + st * STAGEF;
        float* Bs = As + 128 * SP;
#pragma unroll
        for (int l = 0; l < 6; l++) {
            int idx = tid + l * 256;         // 0..1535
            int m = idx / 12;
            int seg = idx - m * 12;          // 12 float4 = 48 floats
            cpa16(smem_u32(As + m * SP + seg * 4),
                  g_A + (size_t)(b0 + m) * KSP + c * CHK + seg * 4);
            cpa16(smem_u32(Bs + m * SP + seg * 4),
                  g_B + (size_t)(j0 + m) * KSP + c * CHK + seg * 4);
        }
        asm volatile("cp.async.commit_group;" ::: "memory");
    };

    const int wm = (wid & 3) * 32;
    const int wn = (wid >> 2) * 64;
    const int grp = lid >> 2;
    const int tig = lid & 3;

    float acc[2][8][4];
#pragma unroll
    for (int mi = 0; mi < 2; mi++)
#pragma unroll
        for (int ni = 0; ni < 8; ni++)
#pragma unroll
            for (int q = 0; q < 4; q++) acc[mi][ni][q] = 0.0f;

    load_chunk(0, 0);

#pragma unroll 1
    for (int c = 0; c < 6; c++) {
        if (c < 5) {
            load_chunk(c + 1, (c + 1) & 1);
            asm volatile("cp.async.wait_group 1;" ::: "memory");
        } else {
            asm volatile("cp.async.wait_group 0;" ::: "memory");
        }
        __syncthreads();

        const float* As = sm + (c & 1) * STAGEF;
        const float* Bs = As + 128 * SP;
#pragma unroll
        for (int ks = 0; ks < 6; ks++) {
            const int k = ks * 8 + tig;
            uint32_t a[2][4];
#pragma unroll
            for (int mi = 0; mi < 2; mi++) {
                int r = wm + mi * 16 + grp;
                a[mi][0] = *(const uint32_t*)(As + r * SP + k);
                a[mi][1] = *(const uint32_t*)(As + (r + 8) * SP + k);
                a[mi][2] = *(const uint32_t*)(As + r * SP + k + 4);
                a[mi][3] = *(const uint32_t*)(As + (r + 8) * SP + k + 4);
            }
            uint32_t b[8][2];
#pragma unroll
            for (int ni = 0; ni < 8; ni++) {
                int n = wn + ni * 8 + grp;
                b[ni][0] = *(const uint32_t*)(Bs + n * SP + k);
                b[ni][1] = *(const uint32_t*)(Bs + n * SP + k + 4);
            }
#pragma unroll
            for (int mi = 0; mi < 2; mi++)
#pragma unroll
                for (int ni = 0; ni < 8; ni++)
                    mma1688_tf32(acc[mi][ni], a[mi], b[ni]);
        }
        __syncthreads();
    }

    // Epilogue: bias add + float2 stores
#pragma unroll
    for (int ni = 0; ni < 8; ni++) {
        const int col = j0 + wn + ni * 8 + 2 * tig;
        const float bx = (col < NPARAM) ? hb2[col] : 0.0f;
        const float by = (col + 1 < NPARAM) ? hb2[col + 1] : 0.0f;
#pragma unroll
        for (int mi = 0; mi < 2; mi++) {
            const int r0 = b0 + wm + mi * 16 + grp;
            *(float2*)(g_params + (size_t)r0 * PPAD + col) =
                make_float2(acc[mi][ni][0] + bx, acc[mi][ni][1] + by);
            *(float2*)(g_params + (size_t)(r0 + 8) * PPAD + col) =
                make_float2(acc[mi][ni][2] + bx, acc[mi][ni][3] + by);
        }
    }
}

// ---------------------------------------------------------------------------
// Adam loop, lane-pair split: 96 threads/sample, 2 samples/block (192 thr).
// Thread (row r, half hf) owns w1[r][hf*24..+24), w2 likewise (48 weight regs).
// Halves combined via __shfl_xor(1) — pairs are (even,odd) lanes, same warp.
// ---------------------------------------------------------------------------
__global__ __launch_bounds__(192, 3) void adam_kernel(float* __restrict__ out) {
    __shared__ __align__(16) float h0s[2][48];
    __shared__ __align__(16) float dh0s[2][48];
    __shared__ __align__(16) float h1s[2][48];
    __shared__ __align__(16) float dh1s[2][48];
    __shared__ __align__(16) float part[2][48];

    const int tid = threadIdx.x;
    const int s = tid / 96;
    const int t = tid - s * 96;
    const int r = t >> 1;
    const int hf = t & 1;
    const int sample = blockIdx.x * 2 + s;

    const float* p = g_params + (size_t)sample * PPAD;

    // Layout: w0[48] b0[48] w1[48x48] b1[48] w2[48x48] b2[48] w3[48] b3
    const float w0i = p[r];
    const float b0i = p[48 + r];
    const float b1i = p[2400 + r];
    const float b2i = p[4752 + r];
    const float w3i = p[4800 + r];

    float w1r[24], w2r[24];
    {
        const float4* p1 = (const float4*)(p + 96 + r * 48 + hf * 24);
        const float4* p2 = (const float4*)(p + 2448 + r * 48 + hf * 24);
#pragma unroll
        for (int q = 0; q < 6; q++) {
            float4 a = p1[q];
            w1r[4 * q + 0] = a.x; w1r[4 * q + 1] = a.y; w1r[4 * q + 2] = a.z; w1r[4 * q + 3] = a.w;
            float4 b = p2[q];
            w2r[4 * q + 0] = b.x; w2r[4 * q + 1] = b.y; w2r[4 * q + 2] = b.z; w2r[4 * q + 3] = b.w;
        }
    }

    float y = 0.0f, mA = 0.0f, vA = 0.0f, pb1 = 1.0f, pb2 = 1.0f;

#pragma unroll 1
    for (int st = 0; st < NSTEPS; st++) {
        // Layer 0 (scalar input)
        float z0 = fmaf(w0i, y, b0i);
        float s0 = sigmoidf(z0);
        if (hf == 0) {
            h0s[s][r]  = z0 * s0;
            dh0s[s][r] = (s0 + z0 * s0 * (1.0f - s0)) * w0i;
        }
        __syncthreads();

        // Layer 1: half-dot then pair-combine
        float accp = (hf == 0) ? b1i : 0.0f;
        float daccp = 0.0f;
        {
            const float4* h4 = (const float4*)&h0s[s][hf * 24];
            const float4* d4 = (const float4*)&dh0s[s][hf * 24];
#pragma unroll
            for (int q = 0; q < 6; q++) {
                float4 hv = h4[q], dv = d4[q];
                accp  = fmaf(w1r[4 * q + 0], hv.x, accp);
                accp  = fmaf(w1r[4 * q + 1], hv.y, accp);
                accp  = fmaf(w1r[4 * q + 2], hv.z, accp);
                accp  = fmaf(w1r[4 * q + 3], hv.w, accp);
                daccp = fmaf(w1r[4 * q + 0], dv.x, daccp);
                daccp = fmaf(w1r[4 * q + 1], dv.y, daccp);
                daccp = fmaf(w1r[4 * q + 2], dv.z, daccp);
                daccp = fmaf(w1r[4 * q + 3], dv.w, daccp);
            }
        }
        float acc  = accp + __shfl_xor_sync(0xffffffffu, accp, 1);
        float dacc = daccp + __shfl_xor_sync(0xffffffffu, daccp, 1);

        float s1 = sigmoidf(acc);
        if (hf == 0) {
            h1s[s][r]  = acc * s1;
            dh1s[s][r] = (s1 + acc * s1 * (1.0f - s1)) * dacc;
        }
        __syncthreads();

        // Layer 2
        accp = (hf == 0) ? b2i : 0.0f;
        daccp = 0.0f;
        {
            const float4* h4 = (const float4*)&h1s[s][hf * 24];
            const float4* d4 = (const float4*)&dh1s[s][hf * 24];
#pragma unroll
            for (int q = 0; q < 6; q++) {
                float4 hv = h4[q], dv = d4[q];
                accp  = fmaf(w2r[4 * q + 0], hv.x, accp);
                accp  = fmaf(w2r[4 * q + 1], hv.y, accp);
                accp  = fmaf(w2r[4 * q + 2], hv.z, accp);
                accp  = fmaf(w2r[4 * q + 3], hv.w, accp);
                daccp = fmaf(w2r[4 * q + 0], dv.x, daccp);
                daccp = fmaf(w2r[4 * q + 1], dv.y, daccp);
                daccp = fmaf(w2r[4 * q + 2], dv.z, daccp);
                daccp = fmaf(w2r[4 * q + 3], dv.w, daccp);
            }
        }
        acc  = accp + __shfl_xor_sync(0xffffffffu, accp, 1);
        dacc = daccp + __shfl_xor_sync(0xffffffffu, daccp, 1);

        float s2 = sigmoidf(acc);
        if (hf == 0)
            part[s][r] = w3i * ((s2 + acc * s2 * (1.0f - s2)) * dacc);
        __syncthreads();

        // g = sum_r part_r  (redundant in all threads: deterministic)
        float g = 0.0f;
        {
            const float4* q4 = (const float4*)part[s];
#pragma unroll
            for (int q = 0; q < 12; q++) {
                float4 pv = q4[q];
                g += ((pv.x + pv.y) + (pv.z + pv.w));
            }
        }

        pb1 *= 0.9f;
        pb2 *= 0.999f;
        mA = 0.9f * mA + 0.1f * g;
        vA = 0.999f * vA + 0.001f * g * g;
        float mh = mA / (1.0f - pb1);
        float vh = vA / (1.0f - pb2);
        y -= 0.1f * mh / (sqrtf(vh) + 1e-8f);
    }

    if (t == 0) out[sample] = y;
}

// ---------------------------------------------------------------------------
extern "C" void kernel_launch(void* const* d_in, const int* in_sizes, int n_in,
                              void* d_out, int out_size) {
    const float* x   = (const float*)d_in[0];   // (8192,1)
    const float* c   = (const float*)d_in[1];   // (8192,1)
    const float* hw1 = (const float*)d_in[2];   // (96,2)
    const float* hb1 = (const float*)d_in[3];   // (96,)
    const float* hw2 = (const float*)d_in[4];   // (4849,96)
    const float* hb2 = (const float*)d_in[5];   // (4849,)
    float* out = (float*)d_out;                 // (8192,1)

    (void)in_sizes; (void)n_in; (void)out_size;

    cudaFuncSetAttribute(gemm_mma_kernel,
                         cudaFuncAttributeMaxDynamicSharedMemorySize, GT_SMEM);

    prep_a_kernel<<<(NB * NH + 255) / 256, 256>>>(x, c, hw1, hb1);
    prep_b_kernel<<<(NPPAD * NH + 255) / 256, 256>>>(hw2);

    dim3 grid(NB / 128, NPPAD / 128);           // (64, 38)
    gemm_mma_kernel<<<grid, 256, GT_SMEM>>>(hb2);

    adam_kernel<<<NB / 2, 192>>>(out);
}

// round 16
// speedup vs baseline: 1.1149x; 1.1149x over previous
#include <cuda_runtime.h>
#include <cstdint>

#define NB 8192
#define NPARAM 4849
#define NPPAD 4864     // padded N (38*128)
#define PPAD 4864      // param row stride
#define NH 96
#define KSP 288        // term-major split K: A=[ah|ah|al], B=[bh|bl|bh]
#define NSTEPS 20

// Device-global scratch (allocation-free per harness rules)
__device__ float g_params[(size_t)NB * PPAD];     // 159 MB
__device__ float g_A[(size_t)NB * KSP];           // 9.4 MB
__device__ float g_B[(size_t)NPPAD * KSP];        // 5.6 MB

__device__ __forceinline__ float sigmoidf(float z) {
    return 1.0f / (1.0f + __expf(-z));
}
__device__ __forceinline__ float tf32_rn(float v) {
    uint32_t t;
    asm("cvt.rna.tf32.f32 %0, %1;" : "=r"(t) : "f"(v));
    return __uint_as_float(t);
}
__device__ __forceinline__ uint32_t smem_u32(const void* p) {
    uint32_t a;
    asm("{ .reg .u64 t; cvta.to.shared.u64 t, %1; cvt.u32.u64 %0, t; }" : "=r"(a) : "l"(p));
    return a;
}
__device__ __forceinline__ void cpa16(uint32_t dst, const void* src) {
    asm volatile("cp.async.ca.shared.global [%0], [%1], 16;" :: "r"(dst), "l"(src));
}

// ---------------------------------------------------------------------------
// Prep A: h = relu(...); tf32 hi/lo split, term-major row [ah | ah | al]
// ---------------------------------------------------------------------------
__global__ void prep_a_kernel(const float* __restrict__ x, const float* __restrict__ c,
                              const float* __restrict__ hw1, const float* __restrict__ hb1) {
    int idx = blockIdx.x * blockDim.x + threadIdx.x;
    if (idx >= NB * NH) return;
    int b = idx / NH;
    int k = idx - b * NH;
    float v = fmaf(hw1[2 * k], x[b], fmaf(hw1[2 * k + 1], c[b], hb1[k]));
    v = fmaxf(v, 0.0f);
    float hi = tf32_rn(v);
    float lo = tf32_rn(v - hi);
    size_t base = (size_t)b * KSP;
    g_A[base + k]       = hi;
    g_A[base + 96 + k]  = hi;
    g_A[base + 192 + k] = lo;
}

// ---------------------------------------------------------------------------
// Prep B: tf32 split of hw2 (rows >= NPARAM zeroed), term-major [bh | bl | bh]
// ---------------------------------------------------------------------------
__global__ void prep_b_kernel(const float* __restrict__ hw2) {
    int idx = blockIdx.x * blockDim.x + threadIdx.x;
    if (idx >= NPPAD * NH) return;
    int j = idx / NH;
    int k = idx - j * NH;
    float w = (j < NPARAM) ? hw2[j * NH + k] : 0.0f;
    float hi = tf32_rn(w);
    float lo = tf32_rn(w - hi);
    size_t base = (size_t)j * KSP;
    g_B[base + k]       = hi;
    g_B[base + 96 + k]  = lo;
    g_B[base + 192 + k] = hi;
}

// ---------------------------------------------------------------------------
// 3xTF32 GEMM, cp.async double-buffered (unchanged from R15 — near MMA floor).
// ---------------------------------------------------------------------------
#define CHK 48
#define SP 52
#define STAGEF (2 * 128 * SP)
#define GT_SMEM (2 * STAGEF * 4)                // 106496 bytes

__device__ __forceinline__ void mma1688_tf32(float* c, const uint32_t* a, const uint32_t* b) {
    asm volatile(
        "mma.sync.aligned.m16n8k8.row.col.f32.tf32.tf32.f32 "
        "{%0,%1,%2,%3}, {%4,%5,%6,%7}, {%8,%9}, {%0,%1,%2,%3};"
        : "+f"(c[0]), "+f"(c[1]), "+f"(c[2]), "+f"(c[3])
        : "r"(a[0]), "r"(a[1]), "r"(a[2]), "r"(a[3]), "r"(b[0]), "r"(b[1]));
}

__global__ __launch_bounds__(256, 2) void gemm_mma_kernel(const float* __restrict__ hb2) {
    extern __shared__ __align__(16) float sm[];

    const int tid = threadIdx.x;
    const int wid = tid >> 5;
    const int lid = tid & 31;
    const int b0 = blockIdx.x * 128;
    const int j0 = blockIdx.y * 128;

    auto load_chunk = [&](int c, int st) {
        float* As = sm + st * STAGEF;
        float* Bs = As + 128 * SP;
#pragma unroll
        for (int l = 0; l < 6; l++) {
            int idx = tid + l * 256;
            int m = idx / 12;
            int seg = idx - m * 12;
            cpa16(smem_u32(As + m * SP + seg * 4),
                  g_A + (size_t)(b0 + m) * KSP + c * CHK + seg * 4);
            cpa16(smem_u32(Bs + m * SP + seg * 4),
                  g_B + (size_t)(j0 + m) * KSP + c * CHK + seg * 4);
        }
        asm volatile("cp.async.commit_group;" ::: "memory");
    };

    const int wm = (wid & 3) * 32;
    const int wn = (wid >> 2) * 64;
    const int grp = lid >> 2;
    const int tig = lid & 3;

    float acc[2][8][4];
#pragma unroll
    for (int mi = 0; mi < 2; mi++)
#pragma unroll
        for (int ni = 0; ni < 8; ni++)
#pragma unroll
            for (int q = 0; q < 4; q++) acc[mi][ni][q] = 0.0f;

    load_chunk(0, 0);

#pragma unroll 1
    for (int c = 0; c < 6; c++) {
        if (c < 5) {
            load_chunk(c + 1, (c + 1) & 1);
            asm volatile("cp.async.wait_group 1;" ::: "memory");
        } else {
            asm volatile("cp.async.wait_group 0;" ::: "memory");
        }
        __syncthreads();

        const float* As = sm + (c & 1) * STAGEF;
        const float* Bs = As + 128 * SP;
#pragma unroll
        for (int ks = 0; ks < 6; ks++) {
            const int k = ks * 8 + tig;
            uint32_t a[2][4];
#pragma unroll
            for (int mi = 0; mi < 2; mi++) {
                int r = wm + mi * 16 + grp;
                a[mi][0] = *(const uint32_t*)(As + r * SP + k);
                a[mi][1] = *(const uint32_t*)(As + (r + 8) * SP + k);
                a[mi][2] = *(const uint32_t*)(As + r * SP + k + 4);
                a[mi][3] = *(const uint32_t*)(As + (r + 8) * SP + k + 4);
            }
            uint32_t b[8][2];
#pragma unroll
            for (int ni = 0; ni < 8; ni++) {
                int n = wn + ni * 8 + grp;
                b[ni][0] = *(const uint32_t*)(Bs + n * SP + k);
                b[ni][1] = *(const uint32_t*)(Bs + n * SP + k + 4);
            }
#pragma unroll
            for (int mi = 0; mi < 2; mi++)
#pragma unroll
                for (int ni = 0; ni < 8; ni++)
                    mma1688_tf32(acc[mi][ni], a[mi], b[ni]);
        }
        __syncthreads();
    }

#pragma unroll
    for (int ni = 0; ni < 8; ni++) {
        const int col = j0 + wn + ni * 8 + 2 * tig;
        const float bx = (col < NPARAM) ? hb2[col] : 0.0f;
        const float by = (col + 1 < NPARAM) ? hb2[col + 1] : 0.0f;
#pragma unroll
        for (int mi = 0; mi < 2; mi++) {
            const int r0 = b0 + wm + mi * 16 + grp;
            *(float2*)(g_params + (size_t)r0 * PPAD + col) =
                make_float2(acc[mi][ni][0] + bx, acc[mi][ni][1] + by);
            *(float2*)(g_params + (size_t)(r0 + 8) * PPAD + col) =
                make_float2(acc[mi][ni][2] + bx, acc[mi][ni][3] + by);
        }
    }
}

// ---------------------------------------------------------------------------
// Adam loop: back to full-row-per-thread (R7 layout) but with 4-way split
// accumulators (8 independent FMA chains of depth 12 instead of 2 of depth 48)
// and 4 samples per block (192 threads) for more warps in flight.
// ---------------------------------------------------------------------------
#define SPB 4   // samples per block

__global__ __launch_bounds__(48 * SPB, 2) void adam_kernel(float* __restrict__ out) {
    __shared__ __align__(16) float h0s[SPB][48];
    __shared__ __align__(16) float dh0s[SPB][48];
    __shared__ __align__(16) float h1s[SPB][48];
    __shared__ __align__(16) float dh1s[SPB][48];
    __shared__ __align__(16) float part[SPB][48];

    const int tid = threadIdx.x;
    const int s = tid / 48;
    const int i = tid - s * 48;
    const int sample = blockIdx.x * SPB + s;

    const float* p = g_params + (size_t)sample * PPAD;

    // Layout: w0[48] b0[48] w1[48x48] b1[48] w2[48x48] b2[48] w3[48] b3
    const float w0i = p[i];
    const float b0i = p[48 + i];
    const float b1i = p[2400 + i];
    const float b2i = p[4752 + i];
    const float w3i = p[4800 + i];

    float w1r[48], w2r[48];
    {
        const float4* p1 = (const float4*)(p + 96 + i * 48);
        const float4* p2 = (const float4*)(p + 2448 + i * 48);
#pragma unroll
        for (int q = 0; q < 12; q++) {
            float4 a = p1[q];
            w1r[4 * q + 0] = a.x; w1r[4 * q + 1] = a.y; w1r[4 * q + 2] = a.z; w1r[4 * q + 3] = a.w;
            float4 b = p2[q];
            w2r[4 * q + 0] = b.x; w2r[4 * q + 1] = b.y; w2r[4 * q + 2] = b.z; w2r[4 * q + 3] = b.w;
        }
    }

    float y = 0.0f, mA = 0.0f, vA = 0.0f, pb1 = 1.0f, pb2 = 1.0f;

#pragma unroll 1
    for (int t = 0; t < NSTEPS; t++) {
        // Layer 0 (scalar input): z0 = w0*y + b0 ; tangent dz0 = w0
        float z0 = fmaf(w0i, y, b0i);
        float s0 = sigmoidf(z0);
        h0s[s][i]  = z0 * s0;
        dh0s[s][i] = (s0 + z0 * s0 * (1.0f - s0)) * w0i;
        __syncthreads();

        // Layer 1: 8 independent FMA chains (4 for value, 4 for tangent)
        float a0 = b1i, a1 = 0.0f, a2 = 0.0f, a3 = 0.0f;
        float d0 = 0.0f, d1 = 0.0f, d2 = 0.0f, d3 = 0.0f;
        {
            const float4* h4 = (const float4*)h0s[s];
            const float4* d4 = (const float4*)dh0s[s];
#pragma unroll
            for (int q = 0; q < 12; q++) {
                float4 hv = h4[q], dv = d4[q];
                a0 = fmaf(w1r[4 * q + 0], hv.x, a0);
                a1 = fmaf(w1r[4 * q + 1], hv.y, a1);
                a2 = fmaf(w1r[4 * q + 2], hv.z, a2);
                a3 = fmaf(w1r[4 * q + 3], hv.w, a3);
                d0 = fmaf(w1r[4 * q + 0], dv.x, d0);
                d1 = fmaf(w1r[4 * q + 1], dv.y, d1);
                d2 = fmaf(w1r[4 * q + 2], dv.z, d2);
                d3 = fmaf(w1r[4 * q + 3], dv.w, d3);
            }
        }
        float acc  = (a0 + a1) + (a2 + a3);
        float dacc = (d0 + d1) + (d2 + d3);

        float s1 = sigmoidf(acc);
        h1s[s][i]  = acc * s1;
        dh1s[s][i] = (s1 + acc * s1 * (1.0f - s1)) * dacc;
        __syncthreads();

        // Layer 2
        a0 = b2i; a1 = 0.0f; a2 = 0.0f; a3 = 0.0f;
        d0 = 0.0f; d1 = 0.0f; d2 = 0.0f; d3 = 0.0f;
        {
            const float4* h4 = (const float4*)h1s[s];
            const float4* d4 = (const float4*)dh1s[s];
#pragma unroll
            for (int q = 0; q < 12; q++) {
                float4 hv = h4[q], dv = d4[q];
                a0 = fmaf(w2r[4 * q + 0], hv.x, a0);
                a1 = fmaf(w2r[4 * q + 1], hv.y, a1);
                a2 = fmaf(w2r[4 * q + 2], hv.z, a2);
                a3 = fmaf(w2r[4 * q + 3], hv.w, a3);
                d0 = fmaf(w2r[4 * q + 0], dv.x, d0);
                d1 = fmaf(w2r[4 * q + 1], dv.y, d1);
                d2 = fmaf(w2r[4 * q + 2], dv.z, d2);
                d3 = fmaf(w2r[4 * q + 3], dv.w, d3);
            }
        }
        acc  = (a0 + a1) + (a2 + a3);
        dacc = (d0 + d1) + (d2 + d3);

        float s2 = sigmoidf(acc);
        // output-layer tangent contribution (b3 drops out of the gradient)
        part[s][i] = w3i * ((s2 + acc * s2 * (1.0f - s2)) * dacc);
        __syncthreads();

        // g = sum_i part_i  (redundant in all threads: deterministic)
        float g0 = 0.0f, g1 = 0.0f, g2 = 0.0f, g3 = 0.0f;
        {
            const float4* q4 = (const float4*)part[s];
#pragma unroll
            for (int q = 0; q < 12; q++) {
                float4 pv = q4[q];
                g0 += pv.x; g1 += pv.y; g2 += pv.z; g3 += pv.w;
            }
        }
        float g = (g0 + g1) + (g2 + g3);

        // Adam update
        pb1 *= 0.9f;
        pb2 *= 0.999f;
        mA = 0.9f * mA + 0.1f * g;
        vA = 0.999f * vA + 0.001f * g * g;
        float mh = mA / (1.0f - pb1);
        float vh = vA / (1.0f - pb2);
        y -= 0.1f * mh / (sqrtf(vh) + 1e-8f);
    }

    if (i == 0) out[sample] = y;
}

// ---------------------------------------------------------------------------
extern "C" void kernel_launch(void* const* d_in, const int* in_sizes, int n_in,
                              void* d_out, int out_size) {
    const float* x   = (const float*)d_in[0];   // (8192,1)
    const float* c   = (const float*)d_in[1];   // (8192,1)
    const float* hw1 = (const float*)d_in[2];   // (96,2)
    const float* hb1 = (const float*)d_in[3];   // (96,)
    const float* hw2 = (const float*)d_in[4];   // (4849,96)
    const float* hb2 = (const float*)d_in[5];   // (4849,)
    float* out = (float*)d_out;                 // (8192,1)

    (void)in_sizes; (void)n_in; (void)out_size;

    cudaFuncSetAttribute(gemm_mma_kernel,
                         cudaFuncAttributeMaxDynamicSharedMemorySize, GT_SMEM);

    prep_a_kernel<<<(NB * NH + 255) / 256, 256>>>(x, c, hw1, hb1);
    prep_b_kernel<<<(NPPAD * NH + 255) / 256, 256>>>(hw2);

    dim3 grid(NB / 128, NPPAD / 128);           // (64, 38)
    gemm_mma_kernel<<<grid, 256, GT_SMEM>>>(hb2);

    adam_kernel<<<NB / SPB, 48 * SPB>>>(out);
}